// round 11
// baseline (speedup 1.0000x reference)
#include <cuda_runtime.h>
#include <math.h>

#define PI_F 3.14159f

// Fixed problem shape: B=4, D=C=256, H=W=64, P=256
#define Bsz 4
#define Dd  256
#define Hh  64
#define Ww  64
#define Pp  256

#define NMLP   128                      // 4 batches x 32 col-groups (1 col/warp) -- stage 1 only
#define NGRID  (NMLP + Bsz * Dd)        // 1152 CTAs

// Stage-1 output (p vectors) + cross-CTA sync state
__device__ float g_p[Bsz * Pp];
__device__ int g_cnt1[Bsz];
__device__ int g_done;

// Sampler shared-plane geometry
#define PAD    2
#define PITCH  69                        // odd pitch (bank-friendly)
#define PROWS  (Hh + 2 * PAD)            // 68
#define NHALO  (2 * 2 * PITCH + Hh * 5)  // rows 0,1,66,67 full + 5 side cells/row

// ---- packed f32x2 helpers (Blackwell FFMA2) ----
typedef unsigned long long ull;
#define FMA2(r, a, b, c) \
    asm("fma.rn.f32x2 %0, %1, %2, %3;" : "=l"(r) : "l"(a), "l"(b), "l"(c))
#define PACK2(r, x) \
    asm("mov.b64 %0, {%1, %1};" : "=l"(r) : "r"(__float_as_uint(x)))
#define UNPACK2(lo, hi, v) \
    asm("mov.b64 {%0, %1}, %2;" : "=r"(lo), "=r"(hi) : "l"(v))

__global__ void __launch_bounds__(256, 6) fused_kernel(
        const float* __restrict__ vol,
        const float* __restrict__ para,
        const float* __restrict__ W_c, const float* __restrict__ b_c,
        const float* __restrict__ W_s, const float* __restrict__ b_s,
        const float* __restrict__ W_r, const float* __restrict__ b_r,
        const float* __restrict__ W_t, const float* __restrict__ b_t,
        float* __restrict__ out) {
    __shared__ float2 sh[PROWS * PITCH];   // 37536 B; MLP path reuses as scratch
    __shared__ float sparam[5];            // scale, cos, sin, t0, t1

    const int bid = blockIdx.x;
    const int tid = threadIdx.x;

    if (bid < NMLP) {
        // ============ MLP stage 1 ONLY: one warp per output column ============
        float* shf = (float*)sh;
        const int b      = bid >> 5;          // 0..3
        const int cgroup = bid & 31;          // 0..31
        const int w      = tid >> 5;          // warp 0..7
        const int lane   = tid & 31;
        const int col    = cgroup * 8 + w;

        shf[tid] = para[b * Pp + tid];
        __syncthreads();

        float acc = 0.0f;
#pragma unroll
        for (int j = 0; j < 8; ++j) {
            const int k = j * 32 + lane;
            acc = fmaf(shf[k], W_c[k * Pp + col], acc);
        }
#pragma unroll
        for (int o = 16; o > 0; o >>= 1)
            acc += __shfl_xor_sync(0xFFFFFFFFu, acc, o);
        if (lane == 0)
            g_p[b * Pp + col] = fmaxf(acc + b_c[col], 0.0f);
        __syncthreads();
        if (tid == 0) {
            __threadfence();
            atomicAdd(&g_cnt1[b], 1);
        }
        // falls through to epilogue; CTA exits quickly, freeing the SM slot
    } else {
        // ============ sample path ============
        const int bd = bid - NMLP;
        const int b  = bd >> 8;
        const int d  = bd & 255;

        // z -> iz (reference op order) — no params needed
        const float gz  = 2.0f * ((float)d / (float)(Dd - 1)) - 1.0f;
        const float iz  = ((gz + 1.0f) * (float)Dd - 1.0f) * 0.5f;
        const float z0f = floorf(iz);
        const float wz1 = iz - z0f;
        const float wz0 = 1.0f - wz1;
        const int   z0  = (int)z0f;

        const float* base = vol + (size_t)b * Dd * Hh * Ww;
        const bool z0ok = (z0 >= 0) && (z0 < Dd);
        const bool z1ok = (z0 + 1 >= 0) && (z0 + 1 < Dd);
        const float4* p0v = (const float4*)(base + (size_t)(z0ok ? z0 : 0) * (Hh * Ww));
        const float4* p1v = (const float4*)(base + (size_t)(z1ok ? z0 + 1 : 0) * (Hh * Ww));
        const float4 zero4 = make_float4(0.f, 0.f, 0.f, 0.f);

        // halo zeroing + interior fill (one phase) — overlaps the MLP stage 1
        for (int i = tid; i < NHALO; i += 256) {
            int row, col;
            if (i < 4 * PITCH) {
                const int r = i / PITCH;
                row = (r < 2) ? r : (Hh + r);
                col = i - r * PITCH;
            } else {
                const int m = i - 4 * PITCH;
                row = 2 + m / 5;
                const int cc = m - (m / 5) * 5;
                col = (cc < 2) ? cc : (Hh + cc);
            }
            sh[row * PITCH + col] = make_float2(0.f, 0.f);
        }
#pragma unroll
        for (int jj = 0; jj < 4; ++jj) {
            const int g  = tid + jj * 256;
            const int y  = g >> 4;
            const int x4 = (g & 15) << 2;
            const float4 a  = z0ok ? p0v[g] : zero4;
            const float4 bb = z1ok ? p1v[g] : zero4;
            float2* dst = &sh[(y + PAD) * PITCH + (x4 + PAD)];
            dst[0] = make_float2(a.x, bb.x);
            dst[1] = make_float2(a.y, bb.y);
            dst[2] = make_float2(a.z, bb.z);
            dst[3] = make_float2(a.w, bb.w);
        }

        // wait for stage-1 p-vector of this batch (MLP CTAs are wave-1-resident)
        if (tid == 0) {
            while (*((volatile int*)&g_cnt1[b]) < 32) __nanosleep(32);
        }
        __syncthreads();   // covers smem fill + flag observation

        // ---- per-CTA head computation: warps 0..3, one dot product each ----
        {
            const int w    = tid >> 5;
            const int lane = tid & 31;
            if (w < 4) {
                const float* wbase;
                int str;
                if      (w == 0) { wbase = W_s + d;             str = Pp;     }
                else if (w == 1) { wbase = W_r + d;             str = Pp;     }
                else if (w == 2) { wbase = W_t + 2 * d;         str = 2 * Pp; }
                else             { wbase = W_t + 2 * d + 1;     str = 2 * Pp; }

                float acc = 0.0f;
#pragma unroll
                for (int j = 0; j < 8; ++j) {
                    const int k = j * 32 + lane;
                    const float pk = __ldcg(&g_p[b * Pp + k]);
                    acc = fmaf(pk, wbase[(size_t)k * str], acc);
                }
#pragma unroll
                for (int o = 16; o > 0; o >>= 1)
                    acc += __shfl_xor_sync(0xFFFFFFFFu, acc, o);

                if (lane == 0) {
                    if (w == 0) {
                        sparam[0] = 2.0f / (1.0f + expf(-(acc + b_s[d])));
                    } else if (w == 1) {
                        const float ang = tanhf(acc + b_r[d]) * PI_F;
                        sparam[1] = cosf(ang);
                        sparam[2] = sinf(ang);
                    } else if (w == 2) {
                        sparam[3] = tanhf(acc + b_t[2 * d]);
                    } else {
                        sparam[4] = tanhf(acc + b_t[2 * d + 1]);
                    }
                }
            }
        }
        __syncthreads();

        const float sc = sparam[0];
        const float c  = sparam[1];
        const float s  = sparam[2];
        const float t0 = sparam[3];
        const float t1 = sparam[4];

        // px constant per thread; py = py0 + 4k  ->  ix, iy affine in k
        const int px  = tid & 63;
        const int py0 = tid >> 6;

        const float gx  = fmaf((float)px,  2.0f / 63.0f, -1.0f);
        const float gy0 = fmaf((float)py0, 2.0f / 63.0f, -1.0f);
        const float dgy = 4.0f * (2.0f / 63.0f);

        const float tx0 = (c * gx - s * gy0) * sc + t0;
        const float ty0 = (s * gx + c * gy0) * sc + t1;
        const float ix0 = fmaf(tx0, 32.0f, 31.5f);     // ((tx+1)*64-1)*0.5
        const float iy0 = fmaf(ty0, 32.0f, 31.5f);
        const float dix = -s * sc * dgy * 32.0f;
        const float diy =  c * sc * dgy * 32.0f;

        float* outp = out + (size_t)bd * (Hh * Ww) + py0 * Ww + px;

        const ull NEG1 = 0xBF800000BF800000ULL;        // (-1.0f, -1.0f)

#pragma unroll 4
        for (int k = 0; k < 16; ++k) {
            const float kf = (float)k;
            const float ix = fmaf(kf, dix, ix0);
            const float iy = fmaf(kf, diy, iy0);

            const float xf = floorf(ix);
            const float yf = floorf(iy);
            const float wx = ix - xf;
            const float wy = iy - yf;

            int x0 = (int)xf;
            int y0 = (int)yf;
            x0 = max(-PAD, min(x0, Ww));               // OOB taps land in zero halo
            y0 = max(-PAD, min(y0, Hh));

            const float2* q = &sh[(y0 + PAD) * PITCH + (x0 + PAD)];
            const ull m00 = *(const ull*)&q[0];
            const ull m01 = *(const ull*)&q[1];
            const ull m10 = *(const ull*)&q[PITCH];
            const ull m11 = *(const ull*)&q[PITCH + 1];

            ull wxp, wyp;
            PACK2(wxp, wx);
            PACK2(wyp, wy);

            // packed bilinear over (plane0, plane1); z-lerp last
            ull d0, h0, d1, h1, dh, g;
            FMA2(d0, NEG1, m00, m01);    // m01 - m00
            FMA2(h0, d0, wxp, m00);
            FMA2(d1, NEG1, m10, m11);    // m11 - m10
            FMA2(h1, d1, wxp, m10);
            FMA2(dh, NEG1, h0, h1);      // h1 - h0
            FMA2(g,  dh, wyp, h0);

            unsigned int glo, ghi;
            UNPACK2(glo, ghi, g);
            outp[k * 4 * Ww] = fmaf(__uint_as_float(ghi), wz1,
                                    __uint_as_float(glo) * wz0);
        }
    }

    // ---- epilogue: last CTA resets sync state for the next graph replay ----
    __syncthreads();
    if (tid == 0) {
        const int v = atomicAdd(&g_done, 1);
        if (v == NGRID - 1) {
#pragma unroll
            for (int i = 0; i < Bsz; ++i) g_cnt1[i] = 0;
            __threadfence();
            g_done = 0;
        }
    }
}

extern "C" void kernel_launch(void* const* d_in, const int* in_sizes, int n_in,
                              void* d_out, int out_size) {
    const float* feature_map = (const float*)d_in[0];
    const float* para_code   = (const float*)d_in[1];
    const float* W_c = (const float*)d_in[2];
    const float* b_c = (const float*)d_in[3];
    const float* W_s = (const float*)d_in[4];
    const float* b_s = (const float*)d_in[5];
    const float* W_r = (const float*)d_in[6];
    const float* b_r = (const float*)d_in[7];
    const float* W_t = (const float*)d_in[8];
    const float* b_t = (const float*)d_in[9];
    float* out = (float*)d_out;

    fused_kernel<<<NGRID, 256>>>(feature_map, para_code,
                                 W_c, b_c, W_s, b_s, W_r, b_r, W_t, b_t, out);
}

// round 16
// speedup vs baseline: 1.3077x; 1.3077x over previous
#include <cuda_runtime.h>
#include <math.h>

#define PI_F 3.14159f

// Fixed problem shape: B=4, D=C=256, H=W=64, P=256
#define Bsz 4
#define Dd  256
#define Hh  64
#define Ww  64
#define Pp  256

// Stage-1 output (p vectors) + per-(b,d) params
__device__ float g_p[Bsz * Pp];
__device__ float g_scale[Bsz * Dd];
__device__ float g_cos[Bsz * Dd];
__device__ float g_sin[Bsz * Dd];
__device__ float g_t0[Bsz * Dd];
__device__ float g_t1[Bsz * Dd];

// ---------------------------------------------------------------------------
// mlp1: p = relu(para @ W_c + b_c). 128 CTAs, one warp per output column.
// ---------------------------------------------------------------------------
__global__ void __launch_bounds__(256) mlp1_kernel(
        const float* __restrict__ para,
        const float* __restrict__ W_c, const float* __restrict__ b_c) {
    __shared__ float spara[Pp];
    const int b      = blockIdx.x >> 5;       // 0..3
    const int cgroup = blockIdx.x & 31;       // 0..31
    const int w      = threadIdx.x >> 5;
    const int lane   = threadIdx.x & 31;
    const int col    = cgroup * 8 + w;

    spara[threadIdx.x] = para[b * Pp + threadIdx.x];
    __syncthreads();

    float acc = 0.0f;
#pragma unroll
    for (int j = 0; j < 8; ++j) {
        const int k = j * 32 + lane;
        acc = fmaf(spara[k], W_c[k * Pp + col], acc);
    }
#pragma unroll
    for (int o = 16; o > 0; o >>= 1)
        acc += __shfl_xor_sync(0xFFFFFFFFu, acc, o);
    if (lane == 0)
        g_p[b * Pp + col] = fmaxf(acc + b_c[col], 0.0f);
}

// ---------------------------------------------------------------------------
// mlp2: 4096 head dot-products, one warp each. 512 CTAs x 8 warps.
// idx = bid*8 + w;  b = idx>>10;  d = (idx&1023)>>2;  h = idx&3.
// ---------------------------------------------------------------------------
__global__ void __launch_bounds__(256) mlp2_kernel(
        const float* __restrict__ W_s, const float* __restrict__ b_s,
        const float* __restrict__ W_r, const float* __restrict__ b_r,
        const float* __restrict__ W_t, const float* __restrict__ b_t) {
    __shared__ float sp[Pp];
    const int w    = threadIdx.x >> 5;
    const int lane = threadIdx.x & 31;
    const int idx  = blockIdx.x * 8 + w;
    const int b    = idx >> 10;
    const int r    = idx & 1023;
    const int d    = r >> 2;
    const int h    = r & 3;

    sp[threadIdx.x] = g_p[b * Pp + threadIdx.x];
    __syncthreads();

    const float* wbase;
    int str;
    if      (h == 0) { wbase = W_s + d;         str = Pp;     }
    else if (h == 1) { wbase = W_r + d;         str = Pp;     }
    else if (h == 2) { wbase = W_t + 2 * d;     str = 2 * Pp; }
    else             { wbase = W_t + 2 * d + 1; str = 2 * Pp; }

    float acc = 0.0f;
#pragma unroll
    for (int j = 0; j < 8; ++j) {
        const int k = j * 32 + lane;
        acc = fmaf(sp[k], wbase[(size_t)k * str], acc);
    }
#pragma unroll
    for (int o = 16; o > 0; o >>= 1)
        acc += __shfl_xor_sync(0xFFFFFFFFu, acc, o);

    if (lane == 0) {
        const int out_idx = b * Dd + d;
        if (h == 0) {
            g_scale[out_idx] = 2.0f / (1.0f + expf(-(acc + b_s[d])));
        } else if (h == 1) {
            const float ang = tanhf(acc + b_r[d]) * PI_F;
            g_cos[out_idx] = cosf(ang);
            g_sin[out_idx] = sinf(ang);
        } else if (h == 2) {
            g_t0[out_idx] = tanhf(acc + b_t[2 * d]);
        } else {
            g_t1[out_idx] = tanhf(acc + b_t[2 * d + 1]);
        }
    }
}

// ---------------------------------------------------------------------------
// sample: one CTA per (b,d). The two z-planes are PRE-BLENDED with (wz0,wz1)
// at fill time into a single scalar plane -> bilinear needs 4 x LDS.32.
// Layout: rows 68 (y-pad 2), pitch 72 floats (x-pad 4 left, 4 right zeroed),
// 16B-aligned float4 interior stores. 19584 B smem -> 8 CTAs/SM.
// ---------------------------------------------------------------------------
#define PITCHF 72
#define XOFF   4
#define YOFF   2
#define PROWSF 68
#define NHALO2 (4 * PITCHF + 64 * 8)     // rows 0,1,66,67 full + 8 side cells/row

__global__ void __launch_bounds__(256, 8) sample_kernel(const float* __restrict__ vol,
                                                        float* __restrict__ out) {
    __shared__ float shp[PROWSF * PITCHF];   // 19584 B

    const int bd  = blockIdx.x;
    const int b   = bd >> 8;
    const int d   = bd & 255;
    const int tid = threadIdx.x;

    const float sc = g_scale[bd];
    const float c  = g_cos[bd];
    const float s  = g_sin[bd];
    const float t0 = g_t0[bd];
    const float t1 = g_t1[bd];

    // z -> iz (reference op order)
    const float gz  = 2.0f * ((float)d / (float)(Dd - 1)) - 1.0f;
    const float iz  = ((gz + 1.0f) * (float)Dd - 1.0f) * 0.5f;
    const float z0f = floorf(iz);
    const float wz1 = iz - z0f;
    const float wz0 = 1.0f - wz1;
    const int   z0  = (int)z0f;

    const float* base = vol + (size_t)b * Dd * Hh * Ww;
    const bool z0ok = (z0 >= 0) && (z0 < Dd);
    const bool z1ok = (z0 + 1 >= 0) && (z0 + 1 < Dd);
    const float4* p0v = (const float4*)(base + (size_t)(z0ok ? z0 : 0) * (Hh * Ww));
    const float4* p1v = (const float4*)(base + (size_t)(z1ok ? z0 + 1 : 0) * (Hh * Ww));
    const float4 zero4 = make_float4(0.f, 0.f, 0.f, 0.f);
    const float f0 = z0ok ? wz0 : 0.0f;      // fold z-validity into blend weights
    const float f1 = z1ok ? wz1 : 0.0f;

    // halo zeroing: rows 0,1,66,67 fully; interior rows cols {0..3, 68..71}
    for (int i = tid; i < NHALO2; i += 256) {
        int row, col;
        if (i < 4 * PITCHF) {
            const int r = i / PITCHF;
            row = (r < 2) ? r : (Hh + r);                 // 0,1,66,67
            col = i - r * PITCHF;
        } else {
            const int m = i - 4 * PITCHF;
            row = 2 + (m >> 3);
            const int cc = m & 7;
            col = (cc < 4) ? cc : (64 + cc);              // 0..3, 68..71
        }
        shp[row * PITCHF + col] = 0.0f;
    }

    // interior fill with pre-blend: 1024 float4 groups
#pragma unroll
    for (int jj = 0; jj < 4; ++jj) {
        const int g  = tid + jj * 256;
        const int y  = g >> 4;
        const int x4 = (g & 15) << 2;
        const float4 a  = z0ok ? p0v[g] : zero4;
        const float4 bb = z1ok ? p1v[g] : zero4;
        float4 v;
        v.x = fmaf(a.x, f0, bb.x * f1);
        v.y = fmaf(a.y, f0, bb.y * f1);
        v.z = fmaf(a.z, f0, bb.z * f1);
        v.w = fmaf(a.w, f0, bb.w * f1);
        *(float4*)&shp[(y + YOFF) * PITCHF + (x4 + XOFF)] = v;
    }
    __syncthreads();

    // px constant per thread; py = py0 + 4k  ->  ix, iy affine in k
    const int px  = tid & 63;
    const int py0 = tid >> 6;

    const float gx  = fmaf((float)px,  2.0f / 63.0f, -1.0f);
    const float gy0 = fmaf((float)py0, 2.0f / 63.0f, -1.0f);
    const float dgy = 4.0f * (2.0f / 63.0f);

    const float tx0 = (c * gx - s * gy0) * sc + t0;
    const float ty0 = (s * gx + c * gy0) * sc + t1;
    const float ix0 = fmaf(tx0, 32.0f, 31.5f);   // ((tx+1)*64-1)*0.5
    const float iy0 = fmaf(ty0, 32.0f, 31.5f);
    const float dix = -s * sc * dgy * 32.0f;
    const float diy =  c * sc * dgy * 32.0f;

    float* outp = out + (size_t)bd * (Hh * Ww) + py0 * Ww + px;

#pragma unroll 4
    for (int k = 0; k < 16; ++k) {
        const float kf = (float)k;
        const float ix = fmaf(kf, dix, ix0);
        const float iy = fmaf(kf, diy, iy0);

        const float xf = floorf(ix);
        const float yf = floorf(iy);
        const float wx = ix - xf;
        const float wy = iy - yf;

        int x0 = (int)xf;
        int y0 = (int)yf;
        x0 = max(-2, min(x0, Ww));               // OOB taps land in zero halo
        y0 = max(-2, min(y0, Hh));

        const float* q = &shp[(y0 + YOFF) * PITCHF + (x0 + XOFF)];
        const float v00 = q[0];
        const float v01 = q[1];
        const float v10 = q[PITCHF];
        const float v11 = q[PITCHF + 1];

        const float h0 = fmaf(v01 - v00, wx, v00);
        const float h1 = fmaf(v11 - v10, wx, v10);
        outp[k * 4 * Ww] = fmaf(h1 - h0, wy, h0);
    }
}

extern "C" void kernel_launch(void* const* d_in, const int* in_sizes, int n_in,
                              void* d_out, int out_size) {
    const float* feature_map = (const float*)d_in[0];
    const float* para_code   = (const float*)d_in[1];
    const float* W_c = (const float*)d_in[2];
    const float* b_c = (const float*)d_in[3];
    const float* W_s = (const float*)d_in[4];
    const float* b_s = (const float*)d_in[5];
    const float* W_r = (const float*)d_in[6];
    const float* b_r = (const float*)d_in[7];
    const float* W_t = (const float*)d_in[8];
    const float* b_t = (const float*)d_in[9];
    float* out = (float*)d_out;

    mlp1_kernel<<<128, 256>>>(para_code, W_c, b_c);
    mlp2_kernel<<<512, 256>>>(W_s, b_s, W_r, b_r, W_t, b_t);
    sample_kernel<<<Bsz * Dd, 256>>>(feature_map, out);
}